// round 1
// baseline (speedup 1.0000x reference)
#include <cuda_runtime.h>
#include <cuda_bf16.h>

// Problem constants (from reference)
#define Bn    32768
#define Gn    25
#define INn   128
#define NCn   3
#define OUTn  75
#define TASKS (Bn * Gn)          // 819200 (b,g) pairs
#define QUADS (TASKS / 4)        // 204800, 4 tasks per warp-iteration

// Shared-memory padding: strides ≡ 8 (mod 32) for conflict-free access
#define K_STRIDE 136             // ints per K row
#define W_STRIDE 392             // floats per weight group (3*128 used + 8 pad)

#define NBLOCK 2048
#define NTHREAD 256

__global__ __launch_bounds__(NTHREAD)
void mlp_rsna9_kernel(const float* __restrict__ x,
                      const int*   __restrict__ Kp,
                      const int*   __restrict__ Vp,
                      const float* __restrict__ Wsp, const float* __restrict__ bsp,
                      const float* __restrict__ Wnf, const float* __restrict__ bnf,
                      const float* __restrict__ Wss, const float* __restrict__ bss,
                      float* __restrict__ out)
{
    __shared__ int   K_s[Gn * K_STRIDE];   // 3400 ints
    __shared__ float W_s[3 * W_STRIDE];    // layout: grp*392 + c*128 + i
    __shared__ int   V_s[OUTn + 1];
    __shared__ float bias_s[12];

    const int tid = threadIdx.x;

    // ---- stage K (padded rows) ----
    for (int idx = tid; idx < Gn * INn; idx += NTHREAD) {
        int g = idx >> 7, i = idx & 127;
        K_s[g * K_STRIDE + i] = Kp[idx];
    }
    // ---- stage W transposed: W_s[grp][c][i] = Wgrp[i*3 + c] ----
    for (int idx = tid; idx < 3 * NCn * INn; idx += NTHREAD) {
        int grp = idx / (NCn * INn);
        int rem = idx - grp * (NCn * INn);
        int c = rem >> 7, i = rem & 127;
        const float* Wg = (grp == 0) ? Wsp : (grp == 1) ? Wnf : Wss;
        W_s[grp * W_STRIDE + c * INn + i] = Wg[i * NCn + c];
    }
    if (tid < OUTn) V_s[tid] = Vp[tid];
    if (tid < 9) {
        int grp = tid / 3, c = tid - grp * 3;
        const float* bg = (grp == 0) ? bsp : (grp == 1) ? bnf : bss;
        bias_s[tid] = bg[c];
    }
    __syncthreads();

    const int lane = tid & 31;
    const int warp = tid >> 5;
    const int sub  = lane & 7;     // position within 8-lane task group
    const int q    = lane >> 3;    // which of 4 tasks this lane serves

    const int warp_global = blockIdx.x * (NTHREAD / 32) + warp;
    const int total_warps = gridDim.x * (NTHREAD / 32);

    for (int quad = warp_global; quad < QUADS; quad += total_warps) {
        const int p   = quad * 4 + q;          // task id = b*25 + g
        const int b   = p / Gn;
        const int g   = p - b * Gn;
        const int grp = (g < 5) ? 0 : (g < 15) ? 1 : 2;

        const float* xrow = x + b * (Gn * INn);
        const int*   Krow = K_s + g * K_STRIDE;
        const float* w0   = W_s + grp * W_STRIDE;

        float s0 = 0.f, s1 = 0.f, s2 = 0.f;

        #pragma unroll
        for (int t = 0; t < 16; t++) {
            const int i  = sub + 8 * t;        // stride-8 lane mapping
            const int kv = Krow[i];            // conflict-free LDS
            const float xv = __ldg(xrow + kv); // coalesced 32B chunks per 8-lane group
            s0 = fmaf(xv, w0[i],           s0);
            s1 = fmaf(xv, w0[INn   + i],   s1);
            s2 = fmaf(xv, w0[2*INn + i],   s2);
        }

        // butterfly reduction within each 8-lane group (xor bits 0..2 only)
        #pragma unroll
        for (int m = 4; m >= 1; m >>= 1) {
            s0 += __shfl_xor_sync(0xffffffffu, s0, m);
            s1 += __shfl_xor_sync(0xffffffffu, s1, m);
            s2 += __shfl_xor_sync(0xffffffffu, s2, m);
        }

        if (sub < NCn) {
            float s = (sub == 0) ? s0 : (sub == 1) ? s1 : s2;
            s += bias_s[grp * 3 + sub];
            out[b * OUTn + V_s[g * NCn + sub]] = s;
        }
    }
}

extern "C" void kernel_launch(void* const* d_in, const int* in_sizes, int n_in,
                              void* d_out, int out_size)
{
    const float* x   = (const float*)d_in[0];
    const int*   K   = (const int*)  d_in[1];
    const int*   V   = (const int*)  d_in[2];
    const float* Wsp = (const float*)d_in[3];
    const float* bsp = (const float*)d_in[4];
    const float* Wnf = (const float*)d_in[5];
    const float* bnf = (const float*)d_in[6];
    const float* Wss = (const float*)d_in[7];
    const float* bss = (const float*)d_in[8];
    float* out = (float*)d_out;

    mlp_rsna9_kernel<<<NBLOCK, NTHREAD>>>(x, K, V, Wsp, bsp, Wnf, bnf, Wss, bss, out);
}

// round 3
// speedup vs baseline: 1.2526x; 1.2526x over previous
#include <cuda_runtime.h>
#include <cuda_bf16.h>

// Problem constants (from reference)
#define Bn    32768
#define Gn    25
#define INn   128
#define NCn   3
#define OUTn  75
#define TASKS (Bn * Gn)          // 819200 (b,g) pairs
#define QUADS (TASKS / 4)        // 204800, 4 tasks per warp-iteration

// Shared-memory padding: strides ≡ 8 (mod 32) floats, and 16B-multiples
#define K_STRIDE 136             // ints per K row
#define W_STRIDE 392             // floats per weight group (3*128 used + 8 pad); 1568B, 16B-mult

#define NBLOCK 2048
#define NTHREAD 256

__global__ __launch_bounds__(NTHREAD)
void mlp_rsna9_kernel(const float* __restrict__ x,
                      const int*   __restrict__ Kp,
                      const int*   __restrict__ Vp,
                      const float* __restrict__ Wsp, const float* __restrict__ bsp,
                      const float* __restrict__ Wnf, const float* __restrict__ bnf,
                      const float* __restrict__ Wss, const float* __restrict__ bss,
                      float* __restrict__ out)
{
    __shared__ int   K_s[Gn * K_STRIDE];            // 3400 ints
    __shared__ __align__(16) float W_s[3 * W_STRIDE]; // grp*392 + c*128 + i
    __shared__ int   V_s[OUTn + 1];
    __shared__ float bias_s[12];
    __shared__ int   Kbase_s[Gn];
    __shared__ int   Kflag_s[Gn];                   // 1 if row contiguous & 16B-aligned

    const int tid = threadIdx.x;

    // ---- stage K (padded rows) ----
    for (int idx = tid; idx < Gn * INn; idx += NTHREAD) {
        int g = idx >> 7, i = idx & 127;
        K_s[g * K_STRIDE + i] = Kp[idx];
    }
    // ---- stage W transposed: W_s[grp][c][i] = Wgrp[i*3 + c] ----
    for (int idx = tid; idx < 3 * NCn * INn; idx += NTHREAD) {
        int grp = idx / (NCn * INn);
        int rem = idx - grp * (NCn * INn);
        int c = rem >> 7, i = rem & 127;
        const float* Wg = (grp == 0) ? Wsp : (grp == 1) ? Wnf : Wss;
        W_s[grp * W_STRIDE + c * INn + i] = Wg[i * NCn + c];
    }
    if (tid < OUTn) V_s[tid] = Vp[tid];
    if (tid < 9) {
        int grp = tid / 3, c = tid - grp * 3;
        const float* bg = (grp == 0) ? bsp : (grp == 1) ? bnf : bss;
        bias_s[tid] = bg[c];
    }
    __syncthreads();

    // ---- per-row contiguity check (one-time; enables float4 fast path) ----
    if (tid < Gn) {
        const int* Krow = K_s + tid * K_STRIDE;
        int base = Krow[0];
        int ok = ((base & 3) == 0) ? 1 : 0;
        #pragma unroll 8
        for (int i = 1; i < INn; i++) ok &= (Krow[i] == base + i) ? 1 : 0;
        Kbase_s[tid] = base;
        Kflag_s[tid] = ok;
    }
    __syncthreads();

    const int lane = tid & 31;
    const int warp = tid >> 5;
    const int sub  = lane & 7;     // position within 8-lane task group
    const int q    = lane >> 3;    // which of 4 tasks this lane serves

    const int warp_global = blockIdx.x * (NTHREAD / 32) + warp;
    const int total_warps = gridDim.x * (NTHREAD / 32);

    for (int quad = warp_global; quad < QUADS; quad += total_warps) {
        const int p   = quad * 4 + q;          // task id = b*25 + g
        const int b   = p / Gn;
        const int g   = p - b * Gn;
        const int grp = (g < 5) ? 0 : (g < 15) ? 1 : 2;

        float s0 = 0.f, s1 = 0.f, s2 = 0.f;

        if (Kflag_s[g]) {
            // ---- fast path: vectorized, K row contiguous ----
            const float4* xv4 = reinterpret_cast<const float4*>(
                                    x + (size_t)b * (Gn * INn) + Kbase_s[g]);
            const float4* w4  = reinterpret_cast<const float4*>(W_s + grp * W_STRIDE);
            #pragma unroll
            for (int t = 0; t < 4; t++) {
                const int f = sub + 8 * t;     // float4 index 0..31
                const float4 xv = __ldg(xv4 + f);
                const float4 wa = w4[f];       // c = 0
                const float4 wb = w4[32 + f];  // c = 1
                const float4 wc = w4[64 + f];  // c = 2
                s0 = fmaf(xv.x, wa.x, s0); s0 = fmaf(xv.y, wa.y, s0);
                s0 = fmaf(xv.z, wa.z, s0); s0 = fmaf(xv.w, wa.w, s0);
                s1 = fmaf(xv.x, wb.x, s1); s1 = fmaf(xv.y, wb.y, s1);
                s1 = fmaf(xv.z, wb.z, s1); s1 = fmaf(xv.w, wb.w, s1);
                s2 = fmaf(xv.x, wc.x, s2); s2 = fmaf(xv.y, wc.y, s2);
                s2 = fmaf(xv.z, wc.z, s2); s2 = fmaf(xv.w, wc.w, s2);
            }
        } else {
            // ---- fallback: honest gather via K ----
            const float* xrow = x + (size_t)b * (Gn * INn);
            const int*   Krow = K_s + g * K_STRIDE;
            const float* w0   = W_s + grp * W_STRIDE;
            #pragma unroll
            for (int t = 0; t < 16; t++) {
                const int i  = sub + 8 * t;
                const int kv = Krow[i];
                const float xv = __ldg(xrow + kv);
                s0 = fmaf(xv, w0[i],           s0);
                s1 = fmaf(xv, w0[INn   + i],   s1);
                s2 = fmaf(xv, w0[2*INn + i],   s2);
            }
        }

        // butterfly reduction within each 8-lane group
        #pragma unroll
        for (int m = 4; m >= 1; m >>= 1) {
            s0 += __shfl_xor_sync(0xffffffffu, s0, m);
            s1 += __shfl_xor_sync(0xffffffffu, s1, m);
            s2 += __shfl_xor_sync(0xffffffffu, s2, m);
        }

        if (sub < NCn) {
            float s = (sub == 0) ? s0 : (sub == 1) ? s1 : s2;
            s += bias_s[grp * 3 + sub];
            out[(size_t)b * OUTn + V_s[g * NCn + sub]] = s;
        }
    }
}

extern "C" void kernel_launch(void* const* d_in, const int* in_sizes, int n_in,
                              void* d_out, int out_size)
{
    const float* x   = (const float*)d_in[0];
    const int*   K   = (const int*)  d_in[1];
    const int*   V   = (const int*)  d_in[2];
    const float* Wsp = (const float*)d_in[3];
    const float* bsp = (const float*)d_in[4];
    const float* Wnf = (const float*)d_in[5];
    const float* bnf = (const float*)d_in[6];
    const float* Wss = (const float*)d_in[7];
    const float* bss = (const float*)d_in[8];
    float* out = (float*)d_out;

    mlp_rsna9_kernel<<<NBLOCK, NTHREAD>>>(x, K, V, Wsp, bsp, Wnf, bnf, Wss, bss, out);
}